// round 5
// baseline (speedup 1.0000x reference)
#include <cuda_runtime.h>

// MeshUnpool: out[b,f,t] = (1/occ[b,t]) * sum_e features[b,f,e] * group[b,e,t]
// group is a ~0.1%-dense 0/1 fp32 mask.
//
// R5: the 4.78 TB/s plateau (invariant across R2/R3/R4 configs) is blamed on
// strided access order (24 KB thread stride, 192-page working set > 128 TLB
// entries, DRAM row thrash). This version streams group PURELY SEQUENTIALLY
// (block-contiguous 16 KB windows, float4) and handles the rare hits with
// warp-cooperative scattered global atomicAdds into out (pre-zeroed).
// ~96K hits -> 6.1M lane-atomics, overlapped with the DRAM stream.

#define BB 4
#define NF 64
#define EE 4000
#define TT 6000

#define NTHREADS 256
#define UNROLL 4
#define NBLOCKS 1184                       // 8 * 148
#define TOT_F4  (BB * EE * TT / 4)         // 24,000,000 float4
#define OUT_F4  (BB * NF * TT / 4)         // 384,000 float4

// 4 MB scratch: transposed features [B][E][NF]
__device__ __align__(16) float g_featT[BB * EE * NF];

// ---------------------------------------------------------------------------
// Kernel 0: zero the output (harness poisons it with 0xAA)
// ---------------------------------------------------------------------------
__global__ void zero_out_kernel(float4* __restrict__ out4) {
    int i = blockIdx.x * blockDim.x + threadIdx.x;
    int stride = gridDim.x * blockDim.x;
    for (; i < OUT_F4; i += stride)
        out4[i] = make_float4(0.f, 0.f, 0.f, 0.f);
}

// ---------------------------------------------------------------------------
// Kernel 1: transpose features [B, NF, E] -> featT [B, E, NF]
// ---------------------------------------------------------------------------
__global__ void transpose_feat_kernel(const float* __restrict__ feat) {
    __shared__ float tile[32][33];
    const int b  = blockIdx.z;
    const int e0 = blockIdx.x * 32;
    const int f0 = blockIdx.y * 32;
    const int tx = threadIdx.x;   // 0..31
    const int ty = threadIdx.y;   // 0..7

#pragma unroll
    for (int j = 0; j < 32; j += 8)
        tile[ty + j][tx] = feat[((size_t)(b * NF + f0 + ty + j)) * EE + e0 + tx];
    __syncthreads();
#pragma unroll
    for (int j = 0; j < 32; j += 8)
        g_featT[((size_t)b * EE + (e0 + ty + j)) * NF + f0 + tx] = tile[tx][ty + j];
}

// ---------------------------------------------------------------------------
// Kernel 2: sequential stream + warp-cooperative sparse scatter
// ---------------------------------------------------------------------------
__device__ __forceinline__ void warp_hit(unsigned fidx, float val, int lane,
                                         const float* __restrict__ occ,
                                         float* __restrict__ out) {
    // decompose linear float index -> (b, e, t); all < 2^32
    const unsigned bet = EE * TT;              // 24,000,000
    const unsigned b   = fidx / bet;
    const unsigned rem = fidx - b * bet;
    const unsigned e   = rem / TT;
    const unsigned t   = rem - e * TT;

    const float occv  = occ[b * TT + t];       // broadcast load (L1/L2 hit)
    const float scale = val / occv;

    const float2* col =
        reinterpret_cast<const float2*>(g_featT + ((size_t)b * EE + e) * NF);
    const float2 f = col[lane];                // 256 B row, L2-resident

    float* obase = out + ((size_t)b * NF + 2 * lane) * TT + t;
    atomicAdd(obase,      f.x * scale);        // no-return -> RED.ADD
    atomicAdd(obase + TT, f.y * scale);
}

__global__ void __launch_bounds__(NTHREADS)
scatter_kernel(const float4* __restrict__ group4,
               const float* __restrict__ occ,
               float* __restrict__ out) {
    const int lane = threadIdx.x & 31;
    const unsigned step = (unsigned)gridDim.x * NTHREADS * UNROLL;

    for (unsigned base = blockIdx.x * (NTHREADS * UNROLL) + threadIdx.x;
         base < TOT_F4 + NTHREADS * UNROLL; base += step) {
        float4 v[UNROLL];
        unsigned idx[UNROLL];
#pragma unroll
        for (int u = 0; u < UNROLL; u++) {
            idx[u] = base + u * NTHREADS;
            v[u] = (idx[u] < TOT_F4)
                       ? __ldcs(&group4[idx[u]])
                       : make_float4(0.f, 0.f, 0.f, 0.f);
        }
#pragma unroll
        for (int u = 0; u < UNROLL; u++) {
            const unsigned any =
                __float_as_uint(v[u].x) | __float_as_uint(v[u].y) |
                __float_as_uint(v[u].z) | __float_as_uint(v[u].w);
            unsigned ballot = __ballot_sync(0xffffffffu, any != 0);
            while (ballot) {               // rare: ~12% of warp-iters, ~1 src
                const int src = __ffs(ballot) - 1;
                ballot &= ballot - 1;
                const unsigned i4 = __shfl_sync(0xffffffffu, idx[u], src);
                float c[4];
                c[0] = __shfl_sync(0xffffffffu, v[u].x, src);
                c[1] = __shfl_sync(0xffffffffu, v[u].y, src);
                c[2] = __shfl_sync(0xffffffffu, v[u].z, src);
                c[3] = __shfl_sync(0xffffffffu, v[u].w, src);
#pragma unroll
                for (int k = 0; k < 4; k++)
                    if (__float_as_uint(c[k]))
                        warp_hit(i4 * 4 + k, c[k], lane, occ, out);
            }
        }
    }
}

extern "C" void kernel_launch(void* const* d_in, const int* in_sizes, int n_in,
                              void* d_out, int out_size) {
    const float* features = (const float*)d_in[0];   // [B, NF, E]
    const float* group    = (const float*)d_in[1];   // [B, E, T]
    const float* occ      = (const float*)d_in[2];   // [B, T]
    float* out = (float*)d_out;                      // [B, NF, T]

    zero_out_kernel<<<592, 256>>>((float4*)out);

    dim3 tgrid(EE / 32, NF / 32, BB);
    dim3 tblk(32, 8);
    transpose_feat_kernel<<<tgrid, tblk>>>(features);

    scatter_kernel<<<NBLOCKS, NTHREADS>>>((const float4*)group, occ, out);
}

// round 6
// speedup vs baseline: 1.0423x; 1.0423x over previous
#include <cuda_runtime.h>

// MeshUnpool: out[b,f,t] = (1/occ[b,t]) * sum_e features[b,f,e] * group[b,e,t]
// group ~0.1%-dense 0/1 mask. Stream group once (384 MB), record sparse hits,
// accumulate via warp-exclusive tt ownership (no hot-path atomics).
//
// R6: single fused kernel. The 4.78 TB/s stream BW is a hard ceiling
// (R2-R5 invariant), so the only recoverable time is the serialized
// transpose pre-kernel (~3 us). Blocks 0..999 transpose one 32x32 feature
// tile at entry (hidden under the 80 us Phase-A stream); Phase B gates on a
// monotonic device counter (satisfied ~75 us before anyone reaches it).

#define BB 4
#define NF 64
#define EE 4000
#define TT 6000

#define TILE_T 16
#define NLANE  (TILE_T / 4)        // 4 float4 lanes
#define NTHREADS 128
#define NSPLIT (NTHREADS / NLANE)  // 32 E-splits
#define EPT    (EE / NSPLIT)       // 125 rows per split
#define UNROLL 5                   // 25 outer iterations
#define NTILES ((TT + TILE_T - 1) / TILE_T)  // 375 -> grid 1500
#define HITS_MAX 512

#define TR_TILES_PER_B 250         // (NF/32) * (EE/32) = 2*125
#define TR_BLOCKS (BB * TR_TILES_PER_B)  // 1000

// 4 MB scratch: transposed features [B][E][NF]
__device__ __align__(16) float g_featT[BB * EE * NF];
// monotonic "featT ready" counter; never reset (identical rewrites on
// replays make early passage benign; call 1 is properly gated).
__device__ int g_tbar = 0;

__global__ void __launch_bounds__(NTHREADS, 10)
unpool_fused_kernel(const float* __restrict__ feat,
                    const float* __restrict__ group,
                    const float* __restrict__ occ,
                    float* __restrict__ out) {
    __shared__ float acc[TILE_T][NF + 1];   // bank(acc[tt][f]) = (tt+f)%32
    __shared__ float inv_occ[TILE_T];
    __shared__ int   hits[HITS_MAX];        // packed (e << 8) | tt
    __shared__ int   nhits;
    __shared__ float ttile[32][33];

    const int bid = blockIdx.x;
    const int tid = threadIdx.x;

    // ---- fused transpose: bids 0..999 each do one 32x32 tile ----
    if (bid < TR_BLOCKS) {
        const int b  = bid / TR_TILES_PER_B;
        const int r  = bid % TR_TILES_PER_B;
        const int f0 = (r / 125) * 32;
        const int e0 = (r % 125) * 32;
        const int tx = tid & 31;            // 0..31
        const int ty = tid >> 5;            // 0..3
#pragma unroll
        for (int j = 0; j < 32; j += 4)     // coalesced read along E
            ttile[ty + j][tx] =
                feat[((size_t)(b * NF + f0 + ty + j)) * EE + e0 + tx];
        __syncthreads();
#pragma unroll
        for (int j = 0; j < 32; j += 4)     // coalesced write along NF
            g_featT[((size_t)b * EE + (e0 + ty + j)) * NF + f0 + tx] =
                ttile[tx][ty + j];
        __threadfence();
        __syncthreads();
        if (tid == 0) atomicAdd(&g_tbar, 1);
    }

    // ---- per-tile init ----
    const int b    = bid / NTILES;
    const int tile = bid % NTILES;
    const int t0   = tile * TILE_T;

    for (int i = tid; i < TILE_T * (NF + 1); i += NTHREADS)
        (&acc[0][0])[i] = 0.0f;
    if (tid < TILE_T)
        inv_occ[tid] = 1.0f / occ[(size_t)b * TT + t0 + tid];
    if (tid == 0) nhits = 0;
    __syncthreads();

    // ---- Phase A: stream group, record nonzero coordinates ----
    const int lane4  = tid & (NLANE - 1);
    const int esplit = tid / NLANE;         // 0..31
    const int tloc   = lane4 * 4;

    {
        const float* gbase = group + (size_t)b * EE * TT + t0 + tloc;
        const int e_begin = esplit * EPT;
        for (int it = 0; it < EPT / UNROLL; it++) {
            const int eb = e_begin + it * UNROLL;
            float4 v[UNROLL];
#pragma unroll
            for (int u = 0; u < UNROLL; u++)
                v[u] = __ldcs(reinterpret_cast<const float4*>(
                    gbase + (size_t)(eb + u) * TT));
            unsigned any = 0;
#pragma unroll
            for (int u = 0; u < UNROLL; u++)
                any |= __float_as_uint(v[u].x) | __float_as_uint(v[u].y) |
                       __float_as_uint(v[u].z) | __float_as_uint(v[u].w);
            if (any) {  // rare (~2% of thread-batches)
#pragma unroll
                for (int u = 0; u < UNROLL; u++) {
                    const float c[4] = {v[u].x, v[u].y, v[u].z, v[u].w};
#pragma unroll
                    for (int k = 0; k < 4; k++) {
                        if (__float_as_uint(c[k])) {
                            int idx = atomicAdd(&nhits, 1);
                            if (idx < HITS_MAX)
                                hits[idx] = ((eb + u) << 8) | (tloc + k);
                        }
                    }
                }
            }
        }
    }
    __syncthreads();

    // ---- gate: featT must be globally complete (satisfied ~75us ago) ----
    if (tid == 0) {
        while (atomicAdd(&g_tbar, 0) < TR_BLOCKS) { }
    }
    __syncthreads();

    // ---- Phase B: warp w exclusively owns tt in [4w, 4w+4) ----
    {
        const int wid  = tid >> 5;          // 0..3
        const int lane = tid & 31;
        const int n = (nhits < HITS_MAX) ? nhits : HITS_MAX;
        for (int i = 0; i < n; i++) {
            const int h  = hits[i];         // LDS broadcast
            const int tt = h & 0xFF;
            if ((tt >> 2) == wid) {
                const int e = h >> 8;
                const float* col = g_featT + ((size_t)b * EE + e) * NF;
                // group values at hits are exactly 1.0
                acc[tt][lane]      += col[lane];
                acc[tt][lane + 32] += col[lane + 32];
            }
        }
    }
    __syncthreads();

    // ---- writeout: out[b, f, t0+tt] = acc[tt][f] * inv_occ[tt] ----
    for (int i = tid; i < NF * TILE_T; i += NTHREADS) {
        const int f  = i / TILE_T;
        const int tt = i % TILE_T;
        out[((size_t)b * NF + f) * TT + t0 + tt] = acc[tt][f] * inv_occ[tt];
    }
}

extern "C" void kernel_launch(void* const* d_in, const int* in_sizes, int n_in,
                              void* d_out, int out_size) {
    const float* features = (const float*)d_in[0];   // [B, NF, E]
    const float* group    = (const float*)d_in[1];   // [B, E, T]
    const float* occ      = (const float*)d_in[2];   // [B, T]
    float* out = (float*)d_out;                      // [B, NF, T]

    unpool_fused_kernel<<<BB * NTILES, NTHREADS>>>(features, group, occ, out);
}

// round 7
// speedup vs baseline: 1.1784x; 1.1306x over previous
#include <cuda_runtime.h>

// MeshUnpool: out[b,f,t] = (1/occ[b,t]) * sum_e features[b,f,e] * group[b,e,t]
// group ~0.1%-dense 0/1 mask. Stream group once (384 MB), record sparse hits,
// accumulate via warp-exclusive tt ownership (no hot-path atomics).
//
// R7: exact R4 structure (best: 86.0us total). Single change: Phase-A group
// loads use ld.global.cv (cache-volatile) instead of ld.global.cs.
// The B300 LTS cap (~6300 B/cyc, ~6.9 TB/s) was measured with LDG.cv;
// all our ~4.8 TB/s plateau rounds used .cs. This isolates load policy.

#define BB 4
#define NF 64
#define EE 4000
#define TT 6000

#define TILE_T 16
#define NLANE  (TILE_T / 4)        // 4 float4 lanes
#define NTHREADS 128
#define NSPLIT (NTHREADS / NLANE)  // 32 E-splits
#define EPT    (EE / NSPLIT)       // 125 rows per split
#define UNROLL 5                   // 25 outer iterations
#define NTILES ((TT + TILE_T - 1) / TILE_T)  // 375 -> grid 1500
#define HITS_MAX 512

// 4 MB scratch for transposed features [B][E][NF].
__device__ __align__(16) float g_featT[BB * EE * NF];

__device__ __forceinline__ float4 ldcv_f4(const float4* p) {
    float4 v;
    asm volatile("ld.global.cv.v4.f32 {%0,%1,%2,%3}, [%4];"
                 : "=f"(v.x), "=f"(v.y), "=f"(v.z), "=f"(v.w)
                 : "l"(p));
    return v;
}

// ---------------------------------------------------------------------------
// Kernel 1: transpose features [B, NF, E] -> featT [B, E, NF]
// ---------------------------------------------------------------------------
__global__ void transpose_feat_kernel(const float* __restrict__ feat) {
    __shared__ float tile[32][33];
    const int b  = blockIdx.z;
    const int e0 = blockIdx.x * 32;
    const int f0 = blockIdx.y * 32;
    const int tx = threadIdx.x;   // 0..31
    const int ty = threadIdx.y;   // 0..7

#pragma unroll
    for (int j = 0; j < 32; j += 8)
        tile[ty + j][tx] = feat[((size_t)(b * NF + f0 + ty + j)) * EE + e0 + tx];
    __syncthreads();
#pragma unroll
    for (int j = 0; j < 32; j += 8)
        g_featT[((size_t)b * EE + (e0 + ty + j)) * NF + f0 + tx] = tile[tx][ty + j];
}

// ---------------------------------------------------------------------------
// Kernel 2: stream + two-phase sparse accumulate
// ---------------------------------------------------------------------------
__global__ void __launch_bounds__(NTHREADS, 10)
unpool_kernel(const float* __restrict__ group,
              const float* __restrict__ occ,
              float* __restrict__ out) {
    __shared__ float acc[TILE_T][NF + 1];   // bank(acc[tt][f]) = (tt+f)%32
    __shared__ float inv_occ[TILE_T];
    __shared__ int   hits[HITS_MAX];        // packed (e << 8) | tt
    __shared__ int   nhits;

    const int b    = blockIdx.x / NTILES;
    const int tile = blockIdx.x % NTILES;
    const int t0   = tile * TILE_T;
    const int tid  = threadIdx.x;

    // init
    for (int i = tid; i < TILE_T * (NF + 1); i += NTHREADS)
        (&acc[0][0])[i] = 0.0f;
    if (tid < TILE_T)
        inv_occ[tid] = 1.0f / occ[(size_t)b * TT + t0 + tid];
    if (tid == 0) nhits = 0;
    __syncthreads();

    // ---- Phase A: stream group, record nonzero coordinates ----
    const int lane4  = tid & (NLANE - 1);   // which float4 inside the t-tile
    const int esplit = tid / NLANE;         // which E-split (0..31)
    const int tloc   = lane4 * 4;

    {
        const float* gbase = group + (size_t)b * EE * TT + t0 + tloc;
        const int e_begin = esplit * EPT;
        for (int it = 0; it < EPT / UNROLL; it++) {
            const int eb = e_begin + it * UNROLL;
            float4 v[UNROLL];
#pragma unroll
            for (int u = 0; u < UNROLL; u++)
                v[u] = ldcv_f4(reinterpret_cast<const float4*>(
                    gbase + (size_t)(eb + u) * TT));
            unsigned any = 0;
#pragma unroll
            for (int u = 0; u < UNROLL; u++)
                any |= __float_as_uint(v[u].x) | __float_as_uint(v[u].y) |
                       __float_as_uint(v[u].z) | __float_as_uint(v[u].w);
            if (any) {  // rare (~2% of thread-batches)
#pragma unroll
                for (int u = 0; u < UNROLL; u++) {
                    const float c[4] = {v[u].x, v[u].y, v[u].z, v[u].w};
#pragma unroll
                    for (int k = 0; k < 4; k++) {
                        if (__float_as_uint(c[k])) {
                            int idx = atomicAdd(&nhits, 1);
                            if (idx < HITS_MAX)
                                hits[idx] = ((eb + u) << 8) | (tloc + k);
                        }
                    }
                }
            }
        }
    }
    __syncthreads();

    // ---- Phase B: warp w exclusively owns tt in [4w, 4w+4) ----
    {
        const int wid  = tid >> 5;          // 0..3
        const int lane = tid & 31;
        const int n = (nhits < HITS_MAX) ? nhits : HITS_MAX;
        for (int i = 0; i < n; i++) {
            const int h  = hits[i];         // LDS broadcast
            const int tt = h & 0xFF;
            if ((tt >> 2) == wid) {
                const int e = h >> 8;
                const float* col = g_featT + ((size_t)b * EE + e) * NF;
                // group values at hits are exactly 1.0
                acc[tt][lane]      += col[lane];
                acc[tt][lane + 32] += col[lane + 32];
            }
        }
    }
    __syncthreads();

    // ---- writeout: out[b, f, t0+tt] = acc[tt][f] * inv_occ[tt] ----
    for (int i = tid; i < NF * TILE_T; i += NTHREADS) {
        const int f  = i / TILE_T;
        const int tt = i % TILE_T;
        out[((size_t)b * NF + f) * TT + t0 + tt] = acc[tt][f] * inv_occ[tt];
    }
}

extern "C" void kernel_launch(void* const* d_in, const int* in_sizes, int n_in,
                              void* d_out, int out_size) {
    const float* features = (const float*)d_in[0];   // [B, NF, E]
    const float* group    = (const float*)d_in[1];   // [B, E, T]
    const float* occ      = (const float*)d_in[2];   // [B, T]
    float* out = (float*)d_out;                      // [B, NF, T]

    dim3 tgrid(EE / 32, NF / 32, BB);
    dim3 tblk(32, 8);
    transpose_feat_kernel<<<tgrid, tblk>>>(features);

    unpool_kernel<<<BB * NTILES, NTHREADS>>>(group, occ, out);
}